// round 14
// baseline (speedup 1.0000x reference)
#include <cuda_runtime.h>
#include <cstdint>

#define BB 16
#define NP 2048
#define NN (BB*NP)   // 32768 total nodes
#define KNN 30

typedef unsigned long long u64;

// ---------------- scratch (device globals; no cudaMalloc allowed) ----------------
__device__ int   g_idx[NN * KNN];           // kNN indices (within batch)
__device__ float g_n2[NN];                  // squared norms
__device__ float g_xt[BB * 64 * NP];        // transposed features [b][c][j]
__device__ float g_P[NN * 64];              // x_j @ W0_bot per node
__device__ float g_A[NN * 64];              // b0 + x_i@W0_top - P[i]
__device__ float g_feat[NN * 192];          // concat [x1 | x2 | x3]
__device__ float g_h1[NN * 1024];
__device__ float g_h2[NN * 256];

// ---------------- helpers ----------------
__device__ __forceinline__ unsigned encf(float f) {
    unsigned u = __float_as_uint(f);
    return (u & 0x80000000u) ? ~u : (u | 0x80000000u);
}
__device__ __forceinline__ u64 splat2(float v) {
    u64 r; asm("mov.b64 %0, {%1, %1};" : "=l"(r) : "f"(v)); return r;
}
__device__ __forceinline__ u64 ffma2(u64 a, u64 b, u64 c) {
    u64 d; asm("fma.rn.f32x2 %0, %1, %2, %3;" : "=l"(d) : "l"(a), "l"(b), "l"(c)); return d;
}
__device__ __forceinline__ float2 unpack2(u64 v) {
    float2 r; asm("mov.b64 {%0, %1}, %2;" : "=f"(r.x), "=f"(r.y) : "l"(v)); return r;
}
__device__ __forceinline__ void ins8(u64* K8, u64 key, u64 lastkey) {
    if (key > lastkey && key < K8[7]) {
        u64 cur = key;
        #pragma unroll
        for (int s = 0; s < 8; s++) {
            u64 a = K8[s];
            u64 mn = a < cur ? a : cur;
            cur = a < cur ? cur : a;
            K8[s] = mn;
        }
    }
}

// ---------------- transpose (+ squared norms) for pos (C=3) ----------------
__global__ void xpose3_kernel(const float* __restrict__ x, float* __restrict__ xt) {
    int g = blockIdx.x * blockDim.x + threadIdx.x;
    if (g < NN) {
        int b = g >> 11, j = g & (NP - 1);
        float a = x[g * 3], bv = x[g * 3 + 1], c = x[g * 3 + 2];
        float* xtb = xt + (size_t)b * 3 * NP;
        xtb[j] = a; xtb[NP + j] = bv; xtb[2 * NP + j] = c;
        float s = 0.f; s += a * a; s += bv * bv; s += c * c;
        g_n2[g] = s;
    }
}

// ---------------- fused dist + select scan ----------------
template<int C>
__device__ __forceinline__ void knn_scan(const float* __restrict__ xb,
                                         const float* __restrict__ xi,
                                         const float* __restrict__ n2b,
                                         int lane, u64* K8, u64 lastkey) {
    for (int jt = 0; jt < NP; jt += 256) {
        u64 a00 = 0ull, a01 = 0ull, a10 = 0ull, a11 = 0ull;
        #pragma unroll
        for (int c = 0; c < C; c++) {
            u64 xs = splat2(xi[c]);
            const float* col = xb + (size_t)c * NP + jt + 4 * lane;
            ulonglong2 q0 = *(const ulonglong2*)col;
            ulonglong2 q1 = *(const ulonglong2*)(col + 128);
            a00 = ffma2(xs, q0.x, a00); a01 = ffma2(xs, q0.y, a01);
            a10 = ffma2(xs, q1.x, a10); a11 = ffma2(xs, q1.y, a11);
        }
        float4 n20 = *(const float4*)&n2b[jt + 4 * lane];
        float4 n21 = *(const float4*)&n2b[jt + 128 + 4 * lane];
        float d[8]; float2 p;
        p = unpack2(a00); d[0] = n20.x - 2.f * p.x; d[1] = n20.y - 2.f * p.y;
        p = unpack2(a01); d[2] = n20.z - 2.f * p.x; d[3] = n20.w - 2.f * p.y;
        p = unpack2(a10); d[4] = n21.x - 2.f * p.x; d[5] = n21.y - 2.f * p.y;
        p = unpack2(a11); d[6] = n21.z - 2.f * p.x; d[7] = n21.w - 2.f * p.y;
        int j0 = jt + 4 * lane;
        #pragma unroll
        for (int q = 0; q < 8; q++) {
            int j = j0 + (q & 3) + ((q >> 2) << 7);
            ins8(K8, ((u64)encf(d[q]) << 32) | (unsigned)j, lastkey);
        }
    }
}

// ---------------- kNN: warp-per-row, no smem dist, no inner syncs ----------------
template<int C>
__global__ __launch_bounds__(256) void knn_kernel(const float* __restrict__ xt) {
    __shared__ float sXi[8 * C];
    int tid = threadIdx.x, b = blockIdx.y, i0 = blockIdx.x * 8;
    const float* xb = xt + (size_t)b * C * NP;
    for (int t = tid; t < 8 * C; t += 256) {
        int i = t & 7, c = t >> 3;
        sXi[i * C + c] = xb[(size_t)c * NP + i0 + i];
    }
    __syncthreads();
    int iw = tid >> 5, lane = tid & 31;
    const float* n2b = g_n2 + b * NP;
    const float* xi = sXi + iw * C;

    u64 K8[8];
    #pragma unroll
    for (int q = 0; q < 8; q++) K8[q] = ~0ull;
    knn_scan<C>(xb, xi, n2b, lane, K8, 0ull);

    int gn = b * NP + i0 + iw;
    int cnt = 8; u64 lastkey = 0;
    for (int it = 0; it < KNN; it++) {
        unsigned hv = (unsigned)(K8[0] >> 32);
        unsigned mv = __reduce_min_sync(0xffffffffu, hv);
        unsigned jc = (hv == mv) ? (unsigned)K8[0] : 0xffffffffu;
        unsigned jmin = __reduce_min_sync(0xffffffffu, jc);
        if (hv == mv && (unsigned)K8[0] == jmin) {
            g_idx[gn * KNN + it] = (int)jmin;
            lastkey = K8[0];
            #pragma unroll
            for (int q = 0; q < 7; q++) K8[q] = K8[q + 1];
            K8[7] = ~0ull;
            if (--cnt == 0) {
                #pragma unroll
                for (int q = 0; q < 8; q++) K8[q] = ~0ull;
                knn_scan<C>(xb, xi, n2b, lane, K8, lastkey);
                cnt = 8;
            }
        }
    }
}

// ---------------- prep (C=3): P[i] = x_i @ W0_bot,  A[i] = b0 + x_i @ W0_top - P[i] ----------------
template<int CIN>
__global__ __launch_bounds__(256)
void prep_kernel(const float* __restrict__ x, int xstride,
                 const float* __restrict__ w0, const float* __restrict__ b0,
                 float* __restrict__ P, float* __restrict__ A) {
    __shared__ float sX[32][CIN + 1];
    __shared__ float sW[2 * CIN * 64];
    __shared__ float sB0[64];
    int tid = threadIdx.x, n0 = blockIdx.x * 32;
    for (int t = tid; t < 2 * CIN * 64; t += 256) sW[t] = w0[t];
    if (tid < 64) sB0[tid] = b0[tid];
    for (int t = tid; t < 32 * CIN; t += 256) {
        int n = t / CIN, c = t % CIN;
        sX[n][c] = x[(size_t)(n0 + n) * xstride + c];
    }
    __syncthreads();
    int n = tid & 31;
    int og = (tid >> 5) * 8;
    u64 accU[4] = {}, accP[4] = {};
    #pragma unroll
    for (int c = 0; c < CIN; c++) {
        u64 xs = splat2(sX[n][c]);
        ulonglong2 wt0 = *(const ulonglong2*)&sW[c * 64 + og];
        ulonglong2 wt1 = *(const ulonglong2*)&sW[c * 64 + og + 4];
        ulonglong2 wb0 = *(const ulonglong2*)&sW[(CIN + c) * 64 + og];
        ulonglong2 wb1 = *(const ulonglong2*)&sW[(CIN + c) * 64 + og + 4];
        accU[0] = ffma2(xs, wt0.x, accU[0]); accU[1] = ffma2(xs, wt0.y, accU[1]);
        accU[2] = ffma2(xs, wt1.x, accU[2]); accU[3] = ffma2(xs, wt1.y, accU[3]);
        accP[0] = ffma2(xs, wb0.x, accP[0]); accP[1] = ffma2(xs, wb0.y, accP[1]);
        accP[2] = ffma2(xs, wb1.x, accP[2]); accP[3] = ffma2(xs, wb1.y, accP[3]);
    }
    float pv[8], av[8];
    #pragma unroll
    for (int q = 0; q < 4; q++) {
        float2 pu = unpack2(accP[q]), uu = unpack2(accU[q]);
        pv[2 * q] = pu.x; pv[2 * q + 1] = pu.y;
        av[2 * q] = sB0[og + 2 * q] + uu.x - pu.x;
        av[2 * q + 1] = sB0[og + 2 * q + 1] + uu.y - pu.y;
    }
    size_t base = (size_t)(n0 + n) * 64 + og;
    *(float4*)&P[base] = make_float4(pv[0], pv[1], pv[2], pv[3]);
    *(float4*)&P[base + 4] = make_float4(pv[4], pv[5], pv[6], pv[7]);
    *(float4*)&A[base] = make_float4(av[0], av[1], av[2], av[3]);
    *(float4*)&A[base + 4] = make_float4(av[4], av[5], av[6], av[7]);
}

// ---------------- fused xpose64 + prep (C=64): one read of the feat slice ----------------
// Stages the 32-node x 64-channel tile once in shared, then:
//  (a) writes transposed xt[b][c][j] + squared norms (xpose64's output, same op order)
//  (b) computes P = x@W0_bot and A = b0 + x@W0_top - P (prep's output, same op order)
__global__ __launch_bounds__(256)
void prep64x_kernel(const float* __restrict__ x, int xstride,
                    const float* __restrict__ w0, const float* __restrict__ b0,
                    float* __restrict__ P, float* __restrict__ A,
                    float* __restrict__ xt) {
    __shared__ float sX[32][65];
    __shared__ float sW[2 * 64 * 64];
    __shared__ float sB0[64];
    int tid = threadIdx.x, n0 = blockIdx.x * 32;
    int b = n0 >> 11, j0 = n0 & (NP - 1);
    for (int t = tid; t < 2 * 64 * 64; t += 256) sW[t] = w0[t];
    if (tid < 64) sB0[tid] = b0[tid];
    for (int t = tid; t < 32 * 64; t += 256) {
        int j = t >> 6, c = t & 63;
        sX[j][c] = x[(size_t)(n0 + j) * xstride + c];
    }
    __syncthreads();

    // (a) transposed write + n2 (identical op order to xpose64_kernel)
    float* xtb = xt + (size_t)b * 64 * NP;
    for (int t = tid; t < 32 * 64; t += 256) {
        int c = t >> 5, j = t & 31;
        xtb[(size_t)c * NP + j0 + j] = sX[j][c];
    }
    if (tid < 32) {
        float acc = 0.f;
        #pragma unroll
        for (int c = 0; c < 64; c++) { float v = sX[tid][c]; acc += v * v; }
        g_n2[b * NP + j0 + tid] = acc;
    }

    // (b) P / A (identical op order to prep_kernel<64>)
    int n = tid & 31;
    int og = (tid >> 5) * 8;
    u64 accU[4] = {}, accP[4] = {};
    #pragma unroll
    for (int c = 0; c < 64; c++) {
        u64 xs = splat2(sX[n][c]);
        ulonglong2 wt0 = *(const ulonglong2*)&sW[c * 64 + og];
        ulonglong2 wt1 = *(const ulonglong2*)&sW[c * 64 + og + 4];
        ulonglong2 wb0 = *(const ulonglong2*)&sW[(64 + c) * 64 + og];
        ulonglong2 wb1 = *(const ulonglong2*)&sW[(64 + c) * 64 + og + 4];
        accU[0] = ffma2(xs, wt0.x, accU[0]); accU[1] = ffma2(xs, wt0.y, accU[1]);
        accU[2] = ffma2(xs, wt1.x, accU[2]); accU[3] = ffma2(xs, wt1.y, accU[3]);
        accP[0] = ffma2(xs, wb0.x, accP[0]); accP[1] = ffma2(xs, wb0.y, accP[1]);
        accP[2] = ffma2(xs, wb1.x, accP[2]); accP[3] = ffma2(xs, wb1.y, accP[3]);
    }
    float pv[8], av[8];
    #pragma unroll
    for (int q = 0; q < 4; q++) {
        float2 pu = unpack2(accP[q]), uu = unpack2(accU[q]);
        pv[2 * q] = pu.x; pv[2 * q + 1] = pu.y;
        av[2 * q] = sB0[og + 2 * q] + uu.x - pu.x;
        av[2 * q + 1] = sB0[og + 2 * q + 1] + uu.y - pu.y;
    }
    size_t base = (size_t)(n0 + n) * 64 + og;
    *(float4*)&P[base] = make_float4(pv[0], pv[1], pv[2], pv[3]);
    *(float4*)&P[base + 4] = make_float4(pv[4], pv[5], pv[6], pv[7]);
    *(float4*)&A[base] = make_float4(av[0], av[1], av[2], av[3]);
    *(float4*)&A[base + 4] = make_float4(av[4], av[5], av[6], av[7]);
}

// ---------------- EdgeConv stage2: 8 nodes/block, 256x64x64 GEMM + shfl-max ----------------
__global__ __launch_bounds__(256)
void edgeconv8_kernel(const float* __restrict__ P, const float* __restrict__ A,
                      const float* __restrict__ w1, const float* __restrict__ b1,
                      float* __restrict__ out, int ostride) {
    extern __shared__ float sm[];
    float* sW1 = sm;            // 4096
    float* sA  = sW1 + 4096;    // 512
    float* sB1 = sA + 512;      // 64
    int*   sJ  = (int*)(sB1 + 64);   // 256
    float* sH  = (float*)(sJ + 256); // 64*256

    int tid = threadIdx.x;
    int gn0 = blockIdx.x * 8;
    int bbase = (gn0 >> 11) << 11;

    for (int t = tid; t < 4096; t += 256) sW1[t] = w1[t];
    for (int t = tid; t < 512; t += 256) sA[t] = A[(size_t)gn0 * 64 + t];
    if (tid < 64) sB1[tid] = b1[tid];
    {
        int nd = tid >> 5, k = tid & 31;
        if (k > 29) k = 29;
        sJ[tid] = bbase + g_idx[(gn0 + nd) * KNN + k];
    }
    __syncthreads();

    #pragma unroll
    for (int it = 0; it < 16; it++) {
        int e = tid;
        int q = it;
        int j = sJ[e];
        int nd = e >> 5;
        float4 p4 = *(const float4*)&P[(size_t)j * 64 + 4 * q];
        float4 a4 = *(const float4*)&sA[nd * 64 + 4 * q];
        float h0 = a4.x + p4.x, h1v = a4.y + p4.y, h2v = a4.z + p4.z, h3v = a4.w + p4.w;
        sH[(4 * q + 0) * 256 + e] = h0 > 0.f ? h0 : 0.f;
        sH[(4 * q + 1) * 256 + e] = h1v > 0.f ? h1v : 0.f;
        sH[(4 * q + 2) * 256 + e] = h2v > 0.f ? h2v : 0.f;
        sH[(4 * q + 3) * 256 + e] = h3v > 0.f ? h3v : 0.f;
    }
    __syncthreads();

    int tx = tid & 31, ty = tid >> 5;

    u64 acc[8][4] = {};
    #pragma unroll
    for (int c = 0; c < 64; c++) {
        float4 e0 = *(const float4*)&sH[c * 256 + 4 * tx];
        float4 e1 = *(const float4*)&sH[c * 256 + 128 + 4 * tx];
        ulonglong2 wq0 = *(const ulonglong2*)&sW1[c * 64 + 8 * ty];
        ulonglong2 wq1 = *(const ulonglong2*)&sW1[c * 64 + 8 * ty + 4];
        u64 wp[4] = {wq0.x, wq0.y, wq1.x, wq1.y};
        u64 ep[8] = {splat2(e0.x), splat2(e0.y), splat2(e0.z), splat2(e0.w),
                     splat2(e1.x), splat2(e1.y), splat2(e1.z), splat2(e1.w)};
        #pragma unroll
        for (int i = 0; i < 8; i++)
            #pragma unroll
            for (int jp = 0; jp < 4; jp++)
                acc[i][jp] = ffma2(ep[i], wp[jp], acc[i][jp]);
    }

    float m1[8], m2[8];
    #pragma unroll
    for (int j = 0; j < 8; j++) { m1[j] = -3.4e38f; m2[j] = -3.4e38f; }
    #pragma unroll
    for (int i = 0; i < 4; i++) {
        #pragma unroll
        for (int jp = 0; jp < 4; jp++) {
            float2 l = unpack2(acc[i][jp]);
            m1[2 * jp] = fmaxf(m1[2 * jp], l.x);
            m1[2 * jp + 1] = fmaxf(m1[2 * jp + 1], l.y);
        }
    }
    #pragma unroll
    for (int i = 4; i < 8; i++) {
        #pragma unroll
        for (int jp = 0; jp < 4; jp++) {
            float2 l = unpack2(acc[i][jp]);
            m2[2 * jp] = fmaxf(m2[2 * jp], l.x);
            m2[2 * jp + 1] = fmaxf(m2[2 * jp + 1], l.y);
        }
    }
    #pragma unroll
    for (int o = 4; o >= 1; o >>= 1) {
        #pragma unroll
        for (int j = 0; j < 8; j++) {
            m1[j] = fmaxf(m1[j], __shfl_down_sync(0xffffffffu, m1[j], o, 8));
            m2[j] = fmaxf(m2[j], __shfl_down_sync(0xffffffffu, m2[j], o, 8));
        }
    }
    if ((tx & 7) == 0) {
        int n1 = tx >> 3, n2 = 4 + (tx >> 3);
        float o1[8], o2[8];
        #pragma unroll
        for (int j = 0; j < 8; j++) {
            o1[j] = m1[j] + sB1[8 * ty + j];
            o2[j] = m2[j] + sB1[8 * ty + j];
        }
        float* d1 = &out[(size_t)(gn0 + n1) * ostride + 8 * ty];
        float* d2 = &out[(size_t)(gn0 + n2) * ostride + 8 * ty];
        *(float4*)d1 = make_float4(o1[0], o1[1], o1[2], o1[3]);
        *(float4*)(d1 + 4) = make_float4(o1[4], o1[5], o1[6], o1[7]);
        *(float4*)d2 = make_float4(o2[0], o2[1], o2[2], o2[3]);
        *(float4*)(d2 + 4) = make_float4(o2[4], o2[5], o2[6], o2[7]);
    }
}

// ---------------- SGEMM mainloop shared machinery (double-buffered smem) ----------------
struct SgemmCtx {
    const float *Aq0, *Aq1, *Wq0, *Wq1;
    int ar0, akq, bk, bn;
};

__device__ __forceinline__ void sgemm_stage(float (*As)[16 * 128], float (*Bs)[16 * 128],
                                            int s, const SgemmCtx& cx,
                                            const float4* ra, const float4* rb) {
    As[s][(4 * cx.akq + 0) * 128 + cx.ar0] = ra[0].x;
    As[s][(4 * cx.akq + 1) * 128 + cx.ar0] = ra[0].y;
    As[s][(4 * cx.akq + 2) * 128 + cx.ar0] = ra[0].z;
    As[s][(4 * cx.akq + 3) * 128 + cx.ar0] = ra[0].w;
    As[s][(4 * cx.akq + 0) * 128 + cx.ar0 + 64] = ra[1].x;
    As[s][(4 * cx.akq + 1) * 128 + cx.ar0 + 64] = ra[1].y;
    As[s][(4 * cx.akq + 2) * 128 + cx.ar0 + 64] = ra[1].z;
    As[s][(4 * cx.akq + 3) * 128 + cx.ar0 + 64] = ra[1].w;
    *(float4*)&Bs[s][cx.bk * 128 + 4 * cx.bn] = rb[0];
    *(float4*)&Bs[s][(cx.bk + 8) * 128 + 4 * cx.bn] = rb[1];
}

__device__ __forceinline__ void sgemm_mainloop(u64 (*acc)[4],
                                               float (*As)[16 * 128], float (*Bs)[16 * 128],
                                               const SgemmCtx& cx, int Nn, int Kk,
                                               int tx, int ty) {
    float4 ra[2], rb[2];
    ra[0] = *(const float4*)cx.Aq0;
    ra[1] = *(const float4*)cx.Aq1;
    rb[0] = *(const float4*)cx.Wq0;
    rb[1] = *(const float4*)cx.Wq1;
    sgemm_stage(As, Bs, 0, cx, ra, rb);
    int cur = 0;
    for (int k0 = 0; k0 < Kk; k0 += 16) {
        bool more = (k0 + 16) < Kk;
        if (more) {
            ra[0] = *(const float4*)(cx.Aq0 + k0 + 16);
            ra[1] = *(const float4*)(cx.Aq1 + k0 + 16);
            rb[0] = *(const float4*)(cx.Wq0 + (size_t)(k0 + 16) * Nn);
            rb[1] = *(const float4*)(cx.Wq1 + (size_t)(k0 + 16) * Nn);
        }
        __syncthreads();
        #pragma unroll
        for (int kk = 0; kk < 16; kk++) {
            float4 a0 = *(const float4*)&As[cur][kk * 128 + 8 * ty];
            float4 a1 = *(const float4*)&As[cur][kk * 128 + 8 * ty + 4];
            ulonglong2 bq0 = *(const ulonglong2*)&Bs[cur][kk * 128 + 8 * tx];
            ulonglong2 bq1 = *(const ulonglong2*)&Bs[cur][kk * 128 + 8 * tx + 4];
            u64 bp[4] = {bq0.x, bq0.y, bq1.x, bq1.y};
            u64 ap[8] = {splat2(a0.x), splat2(a0.y), splat2(a0.z), splat2(a0.w),
                         splat2(a1.x), splat2(a1.y), splat2(a1.z), splat2(a1.w)};
            #pragma unroll
            for (int i = 0; i < 8; i++)
                #pragma unroll
                for (int jp = 0; jp < 4; jp++)
                    acc[i][jp] = ffma2(ap[i], bp[jp], acc[i][jp]);
        }
        if (more) sgemm_stage(As, Bs, cur ^ 1, cx, ra, rb);
        cur ^= 1;
    }
}

__device__ __forceinline__ SgemmCtx sgemm_ctx(const float* A, const float* W,
                                              int m0, int n0, int Nn, int Kk, int tid) {
    SgemmCtx cx;
    cx.ar0 = tid >> 2; cx.akq = tid & 3;
    cx.bk = tid >> 5;  cx.bn = tid & 31;
    cx.Aq0 = A + (size_t)(m0 + cx.ar0) * Kk + 4 * cx.akq;
    cx.Aq1 = A + (size_t)(m0 + cx.ar0 + 64) * Kk + 4 * cx.akq;
    cx.Wq0 = W + (size_t)cx.bk * Nn + n0 + 4 * cx.bn;
    cx.Wq1 = W + (size_t)(cx.bk + 8) * Nn + n0 + 4 * cx.bn;
    return cx;
}

// ---------------- SGEMM: C[M,N] = relu?(A @ W + bias) ----------------
__global__ __launch_bounds__(256)
void sgemm_kernel(const float* __restrict__ A, const float* __restrict__ W,
                  const float* __restrict__ bias, float* __restrict__ C,
                  int M, int Nn, int Kk, int relu) {
    __shared__ float As[2][16 * 128];
    __shared__ float Bs[2][16 * 128];
    int tid = threadIdx.x;
    int m0 = blockIdx.y * 128, n0 = blockIdx.x * 128;
    int tx = tid & 15, ty = tid >> 4;
    SgemmCtx cx = sgemm_ctx(A, W, m0, n0, Nn, Kk, tid);
    u64 acc[8][4] = {};
    sgemm_mainloop(acc, As, Bs, cx, Nn, Kk, tx, ty);

    float4 bv0 = *(const float4*)&bias[n0 + 8 * tx];
    float4 bv1 = *(const float4*)&bias[n0 + 8 * tx + 4];
    float bb[8] = {bv0.x, bv0.y, bv0.z, bv0.w, bv1.x, bv1.y, bv1.z, bv1.w};
    #pragma unroll
    for (int i = 0; i < 8; i++) {
        float o[8];
        #pragma unroll
        for (int jp = 0; jp < 4; jp++) {
            float2 l = unpack2(acc[i][jp]);
            o[2 * jp] = l.x; o[2 * jp + 1] = l.y;
        }
        #pragma unroll
        for (int j = 0; j < 8; j++) {
            float v = o[j] + bb[j];
            o[j] = (relu && v < 0.f) ? 0.f : v;
        }
        *(float4*)&C[(size_t)(m0 + 8 * ty + i) * Nn + n0 + 8 * tx] =
            make_float4(o[0], o[1], o[2], o[3]);
        *(float4*)&C[(size_t)(m0 + 8 * ty + i) * Nn + n0 + 8 * tx + 4] =
            make_float4(o[4], o[5], o[6], o[7]);
    }
}

// ---------------- SGEMM layer3 fused with final 128->3 head ----------------
__global__ __launch_bounds__(256)
void sgemm_fin_kernel(const float* __restrict__ A, const float* __restrict__ W,
                      const float* __restrict__ bias,
                      const float* __restrict__ finw, const float* __restrict__ finb,
                      float* __restrict__ out, int Kk) {
    __shared__ float As[2][16 * 128];
    __shared__ float Bs[2][16 * 128];
    __shared__ float sw[384];
    __shared__ float sb[3];
    const int Nn = 128;
    int tid = threadIdx.x;
    int m0 = blockIdx.y * 128;
    int tx = tid & 15, ty = tid >> 4;
    for (int t = tid; t < 384; t += 256) sw[t] = finw[t];
    if (tid < 3) sb[tid] = finb[tid];
    SgemmCtx cx = sgemm_ctx(A, W, m0, 0, Nn, Kk, tid);
    u64 acc[8][4] = {};
    sgemm_mainloop(acc, As, Bs, cx, Nn, Kk, tx, ty);

    float4 bv0 = *(const float4*)&bias[8 * tx];
    float4 bv1 = *(const float4*)&bias[8 * tx + 4];
    float bb[8] = {bv0.x, bv0.y, bv0.z, bv0.w, bv1.x, bv1.y, bv1.z, bv1.w};
    #pragma unroll
    for (int i = 0; i < 8; i++) {
        float o[8];
        #pragma unroll
        for (int jp = 0; jp < 4; jp++) {
            float2 l = unpack2(acc[i][jp]);
            o[2 * jp] = l.x; o[2 * jp + 1] = l.y;
        }
        float s0 = 0.f, s1 = 0.f, s2 = 0.f;
        #pragma unroll
        for (int j = 0; j < 8; j++) {
            float v = o[j] + bb[j];
            int c = 8 * tx + j;
            s0 += v * sw[c * 3 + 0];
            s1 += v * sw[c * 3 + 1];
            s2 += v * sw[c * 3 + 2];
        }
        #pragma unroll
        for (int off = 8; off >= 1; off >>= 1) {
            s0 += __shfl_down_sync(0xffffffffu, s0, off, 16);
            s1 += __shfl_down_sync(0xffffffffu, s1, off, 16);
            s2 += __shfl_down_sync(0xffffffffu, s2, off, 16);
        }
        if (tx == 0) {
            int m = m0 + 8 * ty + i;
            out[m * 3 + 0] = s0 + sb[0];
            out[m * 3 + 1] = s1 + sb[1];
            out[m * 3 + 2] = s2 + sb[2];
        }
    }
}

// ---------------- launch ----------------
extern "C" void kernel_launch(void* const* d_in, const int* in_sizes, int n_in,
                              void* d_out, int out_size) {
    const float* pos    = (const float*)d_in[0];
    const float* c1_w0  = (const float*)d_in[1];
    const float* c1_b0  = (const float*)d_in[2];
    const float* c1_w1  = (const float*)d_in[3];
    const float* c1_b1  = (const float*)d_in[4];
    const float* c2_w0  = (const float*)d_in[5];
    const float* c2_b0  = (const float*)d_in[6];
    const float* c2_w1  = (const float*)d_in[7];
    const float* c2_b1  = (const float*)d_in[8];
    const float* c3_w0  = (const float*)d_in[9];
    const float* c3_b0  = (const float*)d_in[10];
    const float* c3_w1  = (const float*)d_in[11];
    const float* c3_b1  = (const float*)d_in[12];
    const float* mlp_w0 = (const float*)d_in[13];
    const float* mlp_b0 = (const float*)d_in[14];
    const float* mlp_w1 = (const float*)d_in[15];
    const float* mlp_b1 = (const float*)d_in[16];
    const float* mlp_w2 = (const float*)d_in[17];
    const float* mlp_b2 = (const float*)d_in[18];
    const float* fin_w  = (const float*)d_in[19];
    const float* fin_b  = (const float*)d_in[20];

    float *feat, *h1, *h2, *xt, *Pp, *Ap;
    cudaGetSymbolAddress((void**)&feat, g_feat);
    cudaGetSymbolAddress((void**)&h1, g_h1);
    cudaGetSymbolAddress((void**)&h2, g_h2);
    cudaGetSymbolAddress((void**)&xt, g_xt);
    cudaGetSymbolAddress((void**)&Pp, g_P);
    cudaGetSymbolAddress((void**)&Ap, g_A);

    const int smemEC8 = (4096 + 512 + 64 + 256 + 64 * 256) * 4;  // ~85.3 KB
    cudaFuncSetAttribute(edgeconv8_kernel, cudaFuncAttributeMaxDynamicSharedMemorySize, smemEC8);

    dim3 kgrid3(NP / 8, BB);

    // ---- conv1 (pos, C=3) -> feat[:, 0:64]
    xpose3_kernel<<<NN / 256, 256>>>(pos, xt);
    knn_kernel<3><<<kgrid3, 256>>>(xt);
    prep_kernel<3><<<NN / 32, 256>>>(pos, 3, c1_w0, c1_b0, Pp, Ap);
    edgeconv8_kernel<<<NN / 8, 256, smemEC8>>>(Pp, Ap, c1_w1, c1_b1, feat + 0, 192);

    // ---- conv2 (x1, C=64) -> feat[:, 64:128]
    prep64x_kernel<<<NN / 32, 256>>>(feat, 192, c2_w0, c2_b0, Pp, Ap, xt);
    knn_kernel<64><<<kgrid3, 256>>>(xt);
    edgeconv8_kernel<<<NN / 8, 256, smemEC8>>>(Pp, Ap, c2_w1, c2_b1, feat + 64, 192);

    // ---- conv3 (x2, C=64) -> feat[:, 128:192]
    prep64x_kernel<<<NN / 32, 256>>>(feat + 64, 192, c3_w0, c3_b0, Pp, Ap, xt);
    knn_kernel<64><<<kgrid3, 256>>>(xt);
    edgeconv8_kernel<<<NN / 8, 256, smemEC8>>>(Pp, Ap, c3_w1, c3_b1, feat + 128, 192);

    // ---- MLP
    sgemm_kernel<<<dim3(1024 / 128, NN / 128), 256>>>(feat, mlp_w0, mlp_b0, h1, NN, 1024, 192, 1);
    sgemm_kernel<<<dim3(256 / 128, NN / 128), 256>>>(h1, mlp_w1, mlp_b1, h2, NN, 256, 1024, 1);
    sgemm_fin_kernel<<<dim3(1, NN / 128), 256>>>(h2, mlp_w2, mlp_b2, fin_w, fin_b, (float*)d_out, 256);
}

// round 15
// speedup vs baseline: 1.5937x; 1.5937x over previous
#include <cuda_runtime.h>
#include <cstdint>

#define BB 16
#define NP 2048
#define NN (BB*NP)   // 32768 total nodes
#define KNN 30

typedef unsigned long long u64;

// ---------------- scratch (device globals; no cudaMalloc allowed) ----------------
__device__ int   g_idx[NN * KNN];           // kNN indices (within batch)
__device__ float g_n2[NN];                  // squared norms
__device__ float g_xt[BB * 64 * NP];        // transposed features [b][c][j]
__device__ float g_P[NN * 64];              // x_j @ W0_bot per node
__device__ float g_A[NN * 64];              // b0 + x_i@W0_top - P[i]
__device__ float g_feat[NN * 192];          // concat [x1 | x2 | x3]
__device__ float g_h1[NN * 1024];
__device__ float g_h2[NN * 256];

// ---------------- helpers ----------------
__device__ __forceinline__ unsigned encf(float f) {
    unsigned u = __float_as_uint(f);
    return (u & 0x80000000u) ? ~u : (u | 0x80000000u);
}
__device__ __forceinline__ u64 splat2(float v) {
    u64 r; asm("mov.b64 %0, {%1, %1};" : "=l"(r) : "f"(v)); return r;
}
__device__ __forceinline__ u64 ffma2(u64 a, u64 b, u64 c) {
    u64 d; asm("fma.rn.f32x2 %0, %1, %2, %3;" : "=l"(d) : "l"(a), "l"(b), "l"(c)); return d;
}
__device__ __forceinline__ float2 unpack2(u64 v) {
    float2 r; asm("mov.b64 {%0, %1}, %2;" : "=f"(r.x), "=f"(r.y) : "l"(v)); return r;
}
__device__ __forceinline__ void ins8(u64* K8, u64 key, u64 lastkey) {
    if (key > lastkey && key < K8[7]) {
        u64 cur = key;
        #pragma unroll
        for (int s = 0; s < 8; s++) {
            u64 a = K8[s];
            u64 mn = a < cur ? a : cur;
            cur = a < cur ? cur : a;
            K8[s] = mn;
        }
    }
}

// ---------------- transpose (+ squared norms) ----------------
__global__ void xpose3_kernel(const float* __restrict__ x, float* __restrict__ xt) {
    int g = blockIdx.x * blockDim.x + threadIdx.x;
    if (g < NN) {
        int b = g >> 11, j = g & (NP - 1);
        float a = x[g * 3], bv = x[g * 3 + 1], c = x[g * 3 + 2];
        float* xtb = xt + (size_t)b * 3 * NP;
        xtb[j] = a; xtb[NP + j] = bv; xtb[2 * NP + j] = c;
        float s = 0.f; s += a * a; s += bv * bv; s += c * c;
        g_n2[g] = s;
    }
}

__global__ __launch_bounds__(256)
void xpose64_kernel(const float* __restrict__ x, int stride, float* __restrict__ xt) {
    __shared__ float s[32][65];
    int b = blockIdx.y, j0 = blockIdx.x * 32, tid = threadIdx.x;
    const float* xb = x + (size_t)b * NP * stride;
    for (int t = tid; t < 32 * 64; t += 256) {
        int j = t >> 6, c = t & 63;
        s[j][c] = xb[(size_t)(j0 + j) * stride + c];
    }
    __syncthreads();
    float* xtb = xt + (size_t)b * 64 * NP;
    for (int t = tid; t < 32 * 64; t += 256) {
        int c = t >> 5, j = t & 31;
        xtb[(size_t)c * NP + j0 + j] = s[j][c];
    }
    if (tid < 32) {
        float acc = 0.f;
        #pragma unroll
        for (int c = 0; c < 64; c++) { float v = s[tid][c]; acc += v * v; }
        g_n2[b * NP + j0 + tid] = acc;
    }
}

// ---------------- fused dist + select scan ----------------
template<int C>
__device__ __forceinline__ void knn_scan(const float* __restrict__ xb,
                                         const float* __restrict__ xi,
                                         const float* __restrict__ n2b,
                                         int lane, u64* K8, u64 lastkey) {
    for (int jt = 0; jt < NP; jt += 256) {
        u64 a00 = 0ull, a01 = 0ull, a10 = 0ull, a11 = 0ull;
        #pragma unroll
        for (int c = 0; c < C; c++) {
            u64 xs = splat2(xi[c]);
            const float* col = xb + (size_t)c * NP + jt + 4 * lane;
            ulonglong2 q0 = *(const ulonglong2*)col;
            ulonglong2 q1 = *(const ulonglong2*)(col + 128);
            a00 = ffma2(xs, q0.x, a00); a01 = ffma2(xs, q0.y, a01);
            a10 = ffma2(xs, q1.x, a10); a11 = ffma2(xs, q1.y, a11);
        }
        float4 n20 = *(const float4*)&n2b[jt + 4 * lane];
        float4 n21 = *(const float4*)&n2b[jt + 128 + 4 * lane];
        float d[8]; float2 p;
        p = unpack2(a00); d[0] = n20.x - 2.f * p.x; d[1] = n20.y - 2.f * p.y;
        p = unpack2(a01); d[2] = n20.z - 2.f * p.x; d[3] = n20.w - 2.f * p.y;
        p = unpack2(a10); d[4] = n21.x - 2.f * p.x; d[5] = n21.y - 2.f * p.y;
        p = unpack2(a11); d[6] = n21.z - 2.f * p.x; d[7] = n21.w - 2.f * p.y;
        int j0 = jt + 4 * lane;
        #pragma unroll
        for (int q = 0; q < 8; q++) {
            int j = j0 + (q & 3) + ((q >> 2) << 7);
            ins8(K8, ((u64)encf(d[q]) << 32) | (unsigned)j, lastkey);
        }
    }
}

// ---------------- kNN: warp-per-row, no smem dist, no inner syncs ----------------
template<int C>
__global__ __launch_bounds__(256) void knn_kernel(const float* __restrict__ xt) {
    __shared__ float sXi[8 * C];
    int tid = threadIdx.x, b = blockIdx.y, i0 = blockIdx.x * 8;
    const float* xb = xt + (size_t)b * C * NP;
    for (int t = tid; t < 8 * C; t += 256) {
        int i = t & 7, c = t >> 3;
        sXi[i * C + c] = xb[(size_t)c * NP + i0 + i];
    }
    __syncthreads();
    int iw = tid >> 5, lane = tid & 31;
    const float* n2b = g_n2 + b * NP;
    const float* xi = sXi + iw * C;

    u64 K8[8];
    #pragma unroll
    for (int q = 0; q < 8; q++) K8[q] = ~0ull;
    knn_scan<C>(xb, xi, n2b, lane, K8, 0ull);

    int gn = b * NP + i0 + iw;
    int cnt = 8; u64 lastkey = 0;
    for (int it = 0; it < KNN; it++) {
        unsigned hv = (unsigned)(K8[0] >> 32);
        unsigned mv = __reduce_min_sync(0xffffffffu, hv);
        unsigned jc = (hv == mv) ? (unsigned)K8[0] : 0xffffffffu;
        unsigned jmin = __reduce_min_sync(0xffffffffu, jc);
        if (hv == mv && (unsigned)K8[0] == jmin) {
            g_idx[gn * KNN + it] = (int)jmin;
            lastkey = K8[0];
            #pragma unroll
            for (int q = 0; q < 7; q++) K8[q] = K8[q + 1];
            K8[7] = ~0ull;
            if (--cnt == 0) {
                #pragma unroll
                for (int q = 0; q < 8; q++) K8[q] = ~0ull;
                knn_scan<C>(xb, xi, n2b, lane, K8, lastkey);
                cnt = 8;
            }
        }
    }
}

// ---------------- prep: P[i] = x_i @ W0_bot,  A[i] = b0 + x_i @ W0_top - P[i] ----------------
template<int CIN>
__global__ __launch_bounds__(256)
void prep_kernel(const float* __restrict__ x, int xstride,
                 const float* __restrict__ w0, const float* __restrict__ b0,
                 float* __restrict__ P, float* __restrict__ A) {
    __shared__ float sX[32][CIN + 1];
    __shared__ float sW[2 * CIN * 64];
    __shared__ float sB0[64];
    int tid = threadIdx.x, n0 = blockIdx.x * 32;
    for (int t = tid; t < 2 * CIN * 64; t += 256) sW[t] = w0[t];
    if (tid < 64) sB0[tid] = b0[tid];
    for (int t = tid; t < 32 * CIN; t += 256) {
        int n = t / CIN, c = t % CIN;
        sX[n][c] = x[(size_t)(n0 + n) * xstride + c];
    }
    __syncthreads();
    int n = tid & 31;
    int og = (tid >> 5) * 8;
    u64 accU[4] = {}, accP[4] = {};
    #pragma unroll
    for (int c = 0; c < CIN; c++) {
        u64 xs = splat2(sX[n][c]);
        ulonglong2 wt0 = *(const ulonglong2*)&sW[c * 64 + og];
        ulonglong2 wt1 = *(const ulonglong2*)&sW[c * 64 + og + 4];
        ulonglong2 wb0 = *(const ulonglong2*)&sW[(CIN + c) * 64 + og];
        ulonglong2 wb1 = *(const ulonglong2*)&sW[(CIN + c) * 64 + og + 4];
        accU[0] = ffma2(xs, wt0.x, accU[0]); accU[1] = ffma2(xs, wt0.y, accU[1]);
        accU[2] = ffma2(xs, wt1.x, accU[2]); accU[3] = ffma2(xs, wt1.y, accU[3]);
        accP[0] = ffma2(xs, wb0.x, accP[0]); accP[1] = ffma2(xs, wb0.y, accP[1]);
        accP[2] = ffma2(xs, wb1.x, accP[2]); accP[3] = ffma2(xs, wb1.y, accP[3]);
    }
    float pv[8], av[8];
    #pragma unroll
    for (int q = 0; q < 4; q++) {
        float2 pu = unpack2(accP[q]), uu = unpack2(accU[q]);
        pv[2 * q] = pu.x; pv[2 * q + 1] = pu.y;
        av[2 * q] = sB0[og + 2 * q] + uu.x - pu.x;
        av[2 * q + 1] = sB0[og + 2 * q + 1] + uu.y - pu.y;
    }
    size_t base = (size_t)(n0 + n) * 64 + og;
    *(float4*)&P[base] = make_float4(pv[0], pv[1], pv[2], pv[3]);
    *(float4*)&P[base + 4] = make_float4(pv[4], pv[5], pv[6], pv[7]);
    *(float4*)&A[base] = make_float4(av[0], av[1], av[2], av[3]);
    *(float4*)&A[base + 4] = make_float4(av[4], av[5], av[6], av[7]);
}

// ---------------- EdgeConv stage2: 8 nodes/block, 256x64x64 GEMM + shfl-max ----------------
__global__ __launch_bounds__(256)
void edgeconv8_kernel(const float* __restrict__ P, const float* __restrict__ A,
                      const float* __restrict__ w1, const float* __restrict__ b1,
                      float* __restrict__ out, int ostride) {
    extern __shared__ float sm[];
    float* sW1 = sm;            // 4096
    float* sA  = sW1 + 4096;    // 512
    float* sB1 = sA + 512;      // 64
    int*   sJ  = (int*)(sB1 + 64);   // 256
    float* sH  = (float*)(sJ + 256); // 64*256

    int tid = threadIdx.x;
    int gn0 = blockIdx.x * 8;
    int bbase = (gn0 >> 11) << 11;

    for (int t = tid; t < 4096; t += 256) sW1[t] = w1[t];
    for (int t = tid; t < 512; t += 256) sA[t] = A[(size_t)gn0 * 64 + t];
    if (tid < 64) sB1[tid] = b1[tid];
    {
        int nd = tid >> 5, k = tid & 31;
        if (k > 29) k = 29;
        sJ[tid] = bbase + g_idx[(gn0 + nd) * KNN + k];
    }
    __syncthreads();

    #pragma unroll
    for (int it = 0; it < 16; it++) {
        int e = tid;
        int q = it;
        int j = sJ[e];
        int nd = e >> 5;
        float4 p4 = *(const float4*)&P[(size_t)j * 64 + 4 * q];
        float4 a4 = *(const float4*)&sA[nd * 64 + 4 * q];
        float h0 = a4.x + p4.x, h1v = a4.y + p4.y, h2v = a4.z + p4.z, h3v = a4.w + p4.w;
        sH[(4 * q + 0) * 256 + e] = h0 > 0.f ? h0 : 0.f;
        sH[(4 * q + 1) * 256 + e] = h1v > 0.f ? h1v : 0.f;
        sH[(4 * q + 2) * 256 + e] = h2v > 0.f ? h2v : 0.f;
        sH[(4 * q + 3) * 256 + e] = h3v > 0.f ? h3v : 0.f;
    }
    __syncthreads();

    int tx = tid & 31, ty = tid >> 5;

    u64 acc[8][4] = {};
    #pragma unroll
    for (int c = 0; c < 64; c++) {
        float4 e0 = *(const float4*)&sH[c * 256 + 4 * tx];
        float4 e1 = *(const float4*)&sH[c * 256 + 128 + 4 * tx];
        ulonglong2 wq0 = *(const ulonglong2*)&sW1[c * 64 + 8 * ty];
        ulonglong2 wq1 = *(const ulonglong2*)&sW1[c * 64 + 8 * ty + 4];
        u64 wp[4] = {wq0.x, wq0.y, wq1.x, wq1.y};
        u64 ep[8] = {splat2(e0.x), splat2(e0.y), splat2(e0.z), splat2(e0.w),
                     splat2(e1.x), splat2(e1.y), splat2(e1.z), splat2(e1.w)};
        #pragma unroll
        for (int i = 0; i < 8; i++)
            #pragma unroll
            for (int jp = 0; jp < 4; jp++)
                acc[i][jp] = ffma2(ep[i], wp[jp], acc[i][jp]);
    }

    float m1[8], m2[8];
    #pragma unroll
    for (int j = 0; j < 8; j++) { m1[j] = -3.4e38f; m2[j] = -3.4e38f; }
    #pragma unroll
    for (int i = 0; i < 4; i++) {
        #pragma unroll
        for (int jp = 0; jp < 4; jp++) {
            float2 l = unpack2(acc[i][jp]);
            m1[2 * jp] = fmaxf(m1[2 * jp], l.x);
            m1[2 * jp + 1] = fmaxf(m1[2 * jp + 1], l.y);
        }
    }
    #pragma unroll
    for (int i = 4; i < 8; i++) {
        #pragma unroll
        for (int jp = 0; jp < 4; jp++) {
            float2 l = unpack2(acc[i][jp]);
            m2[2 * jp] = fmaxf(m2[2 * jp], l.x);
            m2[2 * jp + 1] = fmaxf(m2[2 * jp + 1], l.y);
        }
    }
    #pragma unroll
    for (int o = 4; o >= 1; o >>= 1) {
        #pragma unroll
        for (int j = 0; j < 8; j++) {
            m1[j] = fmaxf(m1[j], __shfl_down_sync(0xffffffffu, m1[j], o, 8));
            m2[j] = fmaxf(m2[j], __shfl_down_sync(0xffffffffu, m2[j], o, 8));
        }
    }
    if ((tx & 7) == 0) {
        int n1 = tx >> 3, n2 = 4 + (tx >> 3);
        float o1[8], o2[8];
        #pragma unroll
        for (int j = 0; j < 8; j++) {
            o1[j] = m1[j] + sB1[8 * ty + j];
            o2[j] = m2[j] + sB1[8 * ty + j];
        }
        float* d1 = &out[(size_t)(gn0 + n1) * ostride + 8 * ty];
        float* d2 = &out[(size_t)(gn0 + n2) * ostride + 8 * ty];
        *(float4*)d1 = make_float4(o1[0], o1[1], o1[2], o1[3]);
        *(float4*)(d1 + 4) = make_float4(o1[4], o1[5], o1[6], o1[7]);
        *(float4*)d2 = make_float4(o2[0], o2[1], o2[2], o2[3]);
        *(float4*)(d2 + 4) = make_float4(o2[4], o2[5], o2[6], o2[7]);
    }
}

// ---------------- SGEMM mainloop shared machinery (double-buffered smem) ----------------
struct SgemmCtx {
    const float *Aq0, *Aq1, *Wq0, *Wq1;
    int ar0, akq, bk, bn;
};

__device__ __forceinline__ void sgemm_stage(float (*As)[16 * 128], float (*Bs)[16 * 128],
                                            int s, const SgemmCtx& cx,
                                            const float4* ra, const float4* rb) {
    As[s][(4 * cx.akq + 0) * 128 + cx.ar0] = ra[0].x;
    As[s][(4 * cx.akq + 1) * 128 + cx.ar0] = ra[0].y;
    As[s][(4 * cx.akq + 2) * 128 + cx.ar0] = ra[0].z;
    As[s][(4 * cx.akq + 3) * 128 + cx.ar0] = ra[0].w;
    As[s][(4 * cx.akq + 0) * 128 + cx.ar0 + 64] = ra[1].x;
    As[s][(4 * cx.akq + 1) * 128 + cx.ar0 + 64] = ra[1].y;
    As[s][(4 * cx.akq + 2) * 128 + cx.ar0 + 64] = ra[1].z;
    As[s][(4 * cx.akq + 3) * 128 + cx.ar0 + 64] = ra[1].w;
    *(float4*)&Bs[s][cx.bk * 128 + 4 * cx.bn] = rb[0];
    *(float4*)&Bs[s][(cx.bk + 8) * 128 + 4 * cx.bn] = rb[1];
}

__device__ __forceinline__ void sgemm_mainloop(u64 (*acc)[4],
                                               float (*As)[16 * 128], float (*Bs)[16 * 128],
                                               const SgemmCtx& cx, int Nn, int Kk,
                                               int tx, int ty) {
    float4 ra[2], rb[2];
    ra[0] = *(const float4*)cx.Aq0;
    ra[1] = *(const float4*)cx.Aq1;
    rb[0] = *(const float4*)cx.Wq0;
    rb[1] = *(const float4*)cx.Wq1;
    sgemm_stage(As, Bs, 0, cx, ra, rb);
    int cur = 0;
    for (int k0 = 0; k0 < Kk; k0 += 16) {
        bool more = (k0 + 16) < Kk;
        if (more) {
            ra[0] = *(const float4*)(cx.Aq0 + k0 + 16);
            ra[1] = *(const float4*)(cx.Aq1 + k0 + 16);
            rb[0] = *(const float4*)(cx.Wq0 + (size_t)(k0 + 16) * Nn);
            rb[1] = *(const float4*)(cx.Wq1 + (size_t)(k0 + 16) * Nn);
        }
        __syncthreads();
        #pragma unroll
        for (int kk = 0; kk < 16; kk++) {
            float4 a0 = *(const float4*)&As[cur][kk * 128 + 8 * ty];
            float4 a1 = *(const float4*)&As[cur][kk * 128 + 8 * ty + 4];
            ulonglong2 bq0 = *(const ulonglong2*)&Bs[cur][kk * 128 + 8 * tx];
            ulonglong2 bq1 = *(const ulonglong2*)&Bs[cur][kk * 128 + 8 * tx + 4];
            u64 bp[4] = {bq0.x, bq0.y, bq1.x, bq1.y};
            u64 ap[8] = {splat2(a0.x), splat2(a0.y), splat2(a0.z), splat2(a0.w),
                         splat2(a1.x), splat2(a1.y), splat2(a1.z), splat2(a1.w)};
            #pragma unroll
            for (int i = 0; i < 8; i++)
                #pragma unroll
                for (int jp = 0; jp < 4; jp++)
                    acc[i][jp] = ffma2(ap[i], bp[jp], acc[i][jp]);
        }
        if (more) sgemm_stage(As, Bs, cur ^ 1, cx, ra, rb);
        cur ^= 1;
    }
}

__device__ __forceinline__ SgemmCtx sgemm_ctx(const float* A, const float* W,
                                              int m0, int n0, int Nn, int Kk, int tid) {
    SgemmCtx cx;
    cx.ar0 = tid >> 2; cx.akq = tid & 3;
    cx.bk = tid >> 5;  cx.bn = tid & 31;
    cx.Aq0 = A + (size_t)(m0 + cx.ar0) * Kk + 4 * cx.akq;
    cx.Aq1 = A + (size_t)(m0 + cx.ar0 + 64) * Kk + 4 * cx.akq;
    cx.Wq0 = W + (size_t)cx.bk * Nn + n0 + 4 * cx.bn;
    cx.Wq1 = W + (size_t)(cx.bk + 8) * Nn + n0 + 4 * cx.bn;
    return cx;
}

// ---------------- SGEMM: C[M,N] = relu?(A @ W + bias) ----------------
__global__ __launch_bounds__(256)
void sgemm_kernel(const float* __restrict__ A, const float* __restrict__ W,
                  const float* __restrict__ bias, float* __restrict__ C,
                  int M, int Nn, int Kk, int relu) {
    __shared__ float As[2][16 * 128];
    __shared__ float Bs[2][16 * 128];
    int tid = threadIdx.x;
    int m0 = blockIdx.y * 128, n0 = blockIdx.x * 128;
    int tx = tid & 15, ty = tid >> 4;
    SgemmCtx cx = sgemm_ctx(A, W, m0, n0, Nn, Kk, tid);
    u64 acc[8][4] = {};
    sgemm_mainloop(acc, As, Bs, cx, Nn, Kk, tx, ty);

    float4 bv0 = *(const float4*)&bias[n0 + 8 * tx];
    float4 bv1 = *(const float4*)&bias[n0 + 8 * tx + 4];
    float bb[8] = {bv0.x, bv0.y, bv0.z, bv0.w, bv1.x, bv1.y, bv1.z, bv1.w};
    #pragma unroll
    for (int i = 0; i < 8; i++) {
        float o[8];
        #pragma unroll
        for (int jp = 0; jp < 4; jp++) {
            float2 l = unpack2(acc[i][jp]);
            o[2 * jp] = l.x; o[2 * jp + 1] = l.y;
        }
        #pragma unroll
        for (int j = 0; j < 8; j++) {
            float v = o[j] + bb[j];
            o[j] = (relu && v < 0.f) ? 0.f : v;
        }
        *(float4*)&C[(size_t)(m0 + 8 * ty + i) * Nn + n0 + 8 * tx] =
            make_float4(o[0], o[1], o[2], o[3]);
        *(float4*)&C[(size_t)(m0 + 8 * ty + i) * Nn + n0 + 8 * tx + 4] =
            make_float4(o[4], o[5], o[6], o[7]);
    }
}

// ---------------- SGEMM layer3 fused with final 128->3 head ----------------
__global__ __launch_bounds__(256)
void sgemm_fin_kernel(const float* __restrict__ A, const float* __restrict__ W,
                      const float* __restrict__ bias,
                      const float* __restrict__ finw, const float* __restrict__ finb,
                      float* __restrict__ out, int Kk) {
    __shared__ float As[2][16 * 128];
    __shared__ float Bs[2][16 * 128];
    __shared__ float sw[384];
    __shared__ float sb[3];
    const int Nn = 128;
    int tid = threadIdx.x;
    int m0 = blockIdx.y * 128;
    int tx = tid & 15, ty = tid >> 4;
    for (int t = tid; t < 384; t += 256) sw[t] = finw[t];
    if (tid < 3) sb[tid] = finb[tid];
    SgemmCtx cx = sgemm_ctx(A, W, m0, 0, Nn, Kk, tid);
    u64 acc[8][4] = {};
    sgemm_mainloop(acc, As, Bs, cx, Nn, Kk, tx, ty);

    float4 bv0 = *(const float4*)&bias[8 * tx];
    float4 bv1 = *(const float4*)&bias[8 * tx + 4];
    float bb[8] = {bv0.x, bv0.y, bv0.z, bv0.w, bv1.x, bv1.y, bv1.z, bv1.w};
    #pragma unroll
    for (int i = 0; i < 8; i++) {
        float o[8];
        #pragma unroll
        for (int jp = 0; jp < 4; jp++) {
            float2 l = unpack2(acc[i][jp]);
            o[2 * jp] = l.x; o[2 * jp + 1] = l.y;
        }
        float s0 = 0.f, s1 = 0.f, s2 = 0.f;
        #pragma unroll
        for (int j = 0; j < 8; j++) {
            float v = o[j] + bb[j];
            int c = 8 * tx + j;
            s0 += v * sw[c * 3 + 0];
            s1 += v * sw[c * 3 + 1];
            s2 += v * sw[c * 3 + 2];
        }
        #pragma unroll
        for (int off = 8; off >= 1; off >>= 1) {
            s0 += __shfl_down_sync(0xffffffffu, s0, off, 16);
            s1 += __shfl_down_sync(0xffffffffu, s1, off, 16);
            s2 += __shfl_down_sync(0xffffffffu, s2, off, 16);
        }
        if (tx == 0) {
            int m = m0 + 8 * ty + i;
            out[m * 3 + 0] = s0 + sb[0];
            out[m * 3 + 1] = s1 + sb[1];
            out[m * 3 + 2] = s2 + sb[2];
        }
    }
}

// ---------------- launch ----------------
extern "C" void kernel_launch(void* const* d_in, const int* in_sizes, int n_in,
                              void* d_out, int out_size) {
    const float* pos    = (const float*)d_in[0];
    const float* c1_w0  = (const float*)d_in[1];
    const float* c1_b0  = (const float*)d_in[2];
    const float* c1_w1  = (const float*)d_in[3];
    const float* c1_b1  = (const float*)d_in[4];
    const float* c2_w0  = (const float*)d_in[5];
    const float* c2_b0  = (const float*)d_in[6];
    const float* c2_w1  = (const float*)d_in[7];
    const float* c2_b1  = (const float*)d_in[8];
    const float* c3_w0  = (const float*)d_in[9];
    const float* c3_b0  = (const float*)d_in[10];
    const float* c3_w1  = (const float*)d_in[11];
    const float* c3_b1  = (const float*)d_in[12];
    const float* mlp_w0 = (const float*)d_in[13];
    const float* mlp_b0 = (const float*)d_in[14];
    const float* mlp_w1 = (const float*)d_in[15];
    const float* mlp_b1 = (const float*)d_in[16];
    const float* mlp_w2 = (const float*)d_in[17];
    const float* mlp_b2 = (const float*)d_in[18];
    const float* fin_w  = (const float*)d_in[19];
    const float* fin_b  = (const float*)d_in[20];

    float *feat, *h1, *h2, *xt, *Pp, *Ap;
    cudaGetSymbolAddress((void**)&feat, g_feat);
    cudaGetSymbolAddress((void**)&h1, g_h1);
    cudaGetSymbolAddress((void**)&h2, g_h2);
    cudaGetSymbolAddress((void**)&xt, g_xt);
    cudaGetSymbolAddress((void**)&Pp, g_P);
    cudaGetSymbolAddress((void**)&Ap, g_A);

    const int smemEC8 = (4096 + 512 + 64 + 256 + 64 * 256) * 4;  // ~85.3 KB
    cudaFuncSetAttribute(edgeconv8_kernel, cudaFuncAttributeMaxDynamicSharedMemorySize, smemEC8);

    dim3 kgrid(NP / 8, BB);
    dim3 xgrid(NP / 32, BB);

    // ---- conv1 (pos, C=3) -> feat[:, 0:64]
    xpose3_kernel<<<NN / 256, 256>>>(pos, xt);
    knn_kernel<3><<<kgrid, 256>>>(xt);
    prep_kernel<3><<<NN / 32, 256>>>(pos, 3, c1_w0, c1_b0, Pp, Ap);
    edgeconv8_kernel<<<NN / 8, 256, smemEC8>>>(Pp, Ap, c1_w1, c1_b1, feat + 0, 192);

    // ---- conv2 (x1, C=64) -> feat[:, 64:128]
    xpose64_kernel<<<xgrid, 256>>>(feat, 192, xt);
    knn_kernel<64><<<kgrid, 256>>>(xt);
    prep_kernel<64><<<NN / 32, 256>>>(feat, 192, c2_w0, c2_b0, Pp, Ap);
    edgeconv8_kernel<<<NN / 8, 256, smemEC8>>>(Pp, Ap, c2_w1, c2_b1, feat + 64, 192);

    // ---- conv3 (x2, C=64) -> feat[:, 128:192]
    xpose64_kernel<<<xgrid, 256>>>(feat + 64, 192, xt);
    knn_kernel<64><<<kgrid, 256>>>(xt);
    prep_kernel<64><<<NN / 32, 256>>>(feat + 64, 192, c3_w0, c3_b0, Pp, Ap);
    edgeconv8_kernel<<<NN / 8, 256, smemEC8>>>(Pp, Ap, c3_w1, c3_b1, feat + 128, 192);

    // ---- MLP
    sgemm_kernel<<<dim3(1024 / 128, NN / 128), 256>>>(feat, mlp_w0, mlp_b0, h1, NN, 1024, 192, 1);
    sgemm_kernel<<<dim3(256 / 128, NN / 128), 256>>>(h1, mlp_w1, mlp_b1, h2, NN, 256, 1024, 1);
    sgemm_fin_kernel<<<dim3(1, NN / 128), 256>>>(h2, mlp_w2, mlp_b2, fin_w, fin_b, (float*)d_out, 256);
}